// round 2
// baseline (speedup 1.0000x reference)
#include <cuda_runtime.h>
#include <cstdint>

#define SEQ   1000
#define IDIM  900
#define HDIM  4096
#define WOLD  (HDIM + IDIM + 1)   // 4997, W_out row stride
#define NBLK  148
#define TPB   1024
#define CACHE_ROWS 13
#define LOOP_SMEM ((CACHE_ROWS * HDIM + HDIM) * sizeof(float))   // 229376 B

// ---------------- scratch (static device globals; no allocation) ----------------
__device__ float g_U[SEQ * HDIM];   // W_ih @ inp[t]   (t-major)
__device__ float g_P[SEQ * IDIM];   // bias + input part of readout
__device__ int   g_flags[NBLK];

__device__ __forceinline__ int ld_acq(const int* p) {
    int v;
    asm volatile("ld.acquire.gpu.b32 %0, [%1];" : "=r"(v) : "l"(p) : "memory");
    return v;
}
__device__ __forceinline__ void st_rel(int* p, int v) {
    asm volatile("st.release.gpu.b32 [%0], %1;" :: "l"(p), "r"(v) : "memory");
}

__global__ void reset_kernel() {
    if (threadIdx.x < NBLK) g_flags[threadIdx.x] = 0;
}

// ---------------- persistent recurrence kernel ----------------
// s_{t} = tanh(U[t] + W_hh @ s_{t-1});  states[t] = s_t
// 148 blocks (1/SM). One W_hh row per warp; first CACHE_ROWS rows of each
// block's slice live in SMEM for the whole run; the rest stream from L2 with
// an 8-deep rolling register prefetch (4KB in flight per warp).
__global__ __launch_bounds__(TPB, 1) void esn_loop_kernel(
    const float* __restrict__ W_hh,
    const float* __restrict__ s0,
    float* __restrict__ states)
{
    extern __shared__ float sh[];
    float* w_sh = sh;                      // CACHE_ROWS * HDIM
    float* s_sh = sh + CACHE_ROWS * HDIM;  // HDIM

    const int bid  = blockIdx.x;
    const int tid  = threadIdx.x;
    const int warp = tid >> 5;
    const int lane = tid & 31;

    // 4096 = 148*27 + 100 -> blocks 0..99 get 28 rows, 100..147 get 27
    const int base  = bid * 27 + (bid < 100 ? bid : 100);
    const int nrows = (bid < 100) ? 28 : 27;

    // prologue: cache first CACHE_ROWS rows of this block's slice in SMEM
    {
        const float4* wsrc = (const float4*)(W_hh + (size_t)base * HDIM);
        float4* wdst = (float4*)w_sh;
        for (int i = tid; i < CACHE_ROWS * (HDIM / 4); i += TPB) wdst[i] = wsrc[i];
    }

    const float* s_src = s0;
    const int r = warp;
    const bool active = (r < nrows);
    const bool in_smem = (r < CACHE_ROWS);
    const float4* wrow_g = (const float4*)(W_hh + (size_t)(base + r) * HDIM);
    const float4* wrow_s = (const float4*)(w_sh + r * HDIM);

    for (int t = 0; t < SEQ; ++t) {
        __syncthreads();   // previous-step consumers of s_sh done
        // stage current state vector into SMEM (HDIM/4 == TPB exactly)
        ((float4*)s_sh)[tid] = ((const float4*)s_src)[tid];
        __syncthreads();

        if (active) {
            const float u = g_U[(size_t)t * HDIM + base + r];  // uniform broadcast
            const float4* sv = (const float4*)s_sh;
            float acc = 0.f;

            if (in_smem) {
                #pragma unroll 8
                for (int kk = lane; kk < HDIM / 4; kk += 32) {
                    float4 a = wrow_s[kk];
                    float4 s = sv[kk];
                    acc = fmaf(a.x, s.x, acc); acc = fmaf(a.y, s.y, acc);
                    acc = fmaf(a.z, s.z, acc); acc = fmaf(a.w, s.w, acc);
                }
            } else {
                float4 wb[8];
                #pragma unroll
                for (int j = 0; j < 8; ++j) wb[j] = wrow_g[lane + j * 32];
                #pragma unroll
                for (int g = 0; g < 4; ++g) {
                    #pragma unroll
                    for (int j = 0; j < 8; ++j) {
                        float4 a = wb[j];
                        if (g < 3) wb[j] = wrow_g[lane + ((g + 1) * 8 + j) * 32];
                        float4 s = sv[lane + (g * 8 + j) * 32];
                        acc = fmaf(a.x, s.x, acc); acc = fmaf(a.y, s.y, acc);
                        acc = fmaf(a.z, s.z, acc); acc = fmaf(a.w, s.w, acc);
                    }
                }
            }

            #pragma unroll
            for (int off = 16; off; off >>= 1)
                acc += __shfl_xor_sync(0xffffffffu, acc, off);

            if (lane == 0)
                states[(size_t)t * HDIM + base + r] = tanhf(acc + u);
        }

        // grid barrier: release flag, acquire-poll all flags (pure spin)
        __syncthreads();
        if (t < SEQ - 1) {
            if (tid == 0) { __threadfence(); st_rel(&g_flags[bid], t + 1); }
            if (tid < NBLK) {
                while (ld_acq(&g_flags[tid]) <= t) { }
            }
            __syncthreads();
        }

        s_src = states + (size_t)t * HDIM;
    }
}

// ---------------- fp32 GEMM: C[n][m] = (bias[m]) + (Cadd[n][m]) + sum_k A[m][k]*B[n][k]
// A: M x K row stride lda (scalar loads — may be unaligned base / odd lda)
// B: N x K row stride ldb (float4 when aligned)
// 256 threads, BMxBN tile, BK=8, (BM/16)x(BN/16) microtile per thread.
template<int BM, int BN>
__global__ __launch_bounds__(256) void gemm_nt(
    const float* __restrict__ A, int lda,
    const float* __restrict__ B, int ldb,
    float* __restrict__ C, int ldc,
    const float* __restrict__ Cadd,
    const float* __restrict__ bias, int bias_stride,
    int M, int N, int K)
{
    constexpr int BK = 8;
    constexpr int TM = BM / 16;
    constexpr int TN = BN / 16;
    __shared__ float As[BK][BM + 4];
    __shared__ float Bs[BK][BN + 4];

    const int tid = threadIdx.x;
    const int tx = tid & 15;
    const int ty = tid >> 4;
    const int m0 = blockIdx.x * BM;
    const int n0 = blockIdx.y * BN;

    const bool b_vec = ((reinterpret_cast<uintptr_t>(B) & 15) == 0) && ((ldb & 3) == 0);

    float acc[TM][TN];
    #pragma unroll
    for (int i = 0; i < TM; ++i)
        #pragma unroll
        for (int j = 0; j < TN; ++j) acc[i][j] = 0.f;

    for (int kt = 0; kt < K; kt += BK) {
        // ---- load A tile (BM x 8) transposed into As, scalar loads ----
        #pragma unroll
        for (int i = tid; i < BM * 2; i += 256) {
            int m = i >> 1;
            int kq = (i & 1) * 4;
            int gm = m0 + m;
            float v0 = 0.f, v1 = 0.f, v2 = 0.f, v3 = 0.f;
            if (gm < M) {
                const float* p = A + (size_t)gm * lda + (kt + kq);
                int rem = K - (kt + kq);
                if (rem > 0) v0 = p[0];
                if (rem > 1) v1 = p[1];
                if (rem > 2) v2 = p[2];
                if (rem > 3) v3 = p[3];
            }
            As[kq + 0][m] = v0; As[kq + 1][m] = v1;
            As[kq + 2][m] = v2; As[kq + 3][m] = v3;
        }
        // ---- load B tile (BN x 8) transposed into Bs ----
        #pragma unroll
        for (int i = tid; i < BN * 2; i += 256) {
            int n = i >> 1;
            int kq = (i & 1) * 4;
            int gn = n0 + n;
            int gk = kt + kq;
            float v0 = 0.f, v1 = 0.f, v2 = 0.f, v3 = 0.f;
            if (gn < N) {
                const float* p = B + (size_t)gn * ldb + gk;
                int rem = K - gk;
                if (b_vec && rem >= 4) {
                    float4 v = *(const float4*)p;
                    v0 = v.x; v1 = v.y; v2 = v.z; v3 = v.w;
                } else {
                    if (rem > 0) v0 = p[0];
                    if (rem > 1) v1 = p[1];
                    if (rem > 2) v2 = p[2];
                    if (rem > 3) v3 = p[3];
                }
            }
            Bs[kq + 0][n] = v0; Bs[kq + 1][n] = v1;
            Bs[kq + 2][n] = v2; Bs[kq + 3][n] = v3;
        }
        __syncthreads();

        #pragma unroll
        for (int kk = 0; kk < BK; ++kk) {
            float a[TM], b[TN];
            #pragma unroll
            for (int i = 0; i < TM; ++i) a[i] = As[kk][ty * TM + i];
            #pragma unroll
            for (int j = 0; j < TN; ++j) b[j] = Bs[kk][tx * TN + j];
            #pragma unroll
            for (int i = 0; i < TM; ++i)
                #pragma unroll
                for (int j = 0; j < TN; ++j)
                    acc[i][j] = fmaf(a[i], b[j], acc[i][j]);
        }
        __syncthreads();
    }

    // ---- epilogue ----
    #pragma unroll
    for (int i = 0; i < TM; ++i) {
        int gm = m0 + ty * TM + i;
        if (gm >= M) continue;
        float bv = bias ? bias[(size_t)gm * bias_stride] : 0.f;
        #pragma unroll
        for (int j = 0; j < TN; ++j) {
            int gn = n0 + tx * TN + j;
            if (gn >= N) continue;
            float v = acc[i][j] + bv;
            if (Cadd) v += Cadd[(size_t)gn * ldc + gm];
            C[(size_t)gn * ldc + gm] = v;
        }
    }
}

// ---------------- launch ----------------
extern "C" void kernel_launch(void* const* d_in, const int* in_sizes, int n_in,
                              void* d_out, int out_size)
{
    const float* inputs = (const float*)d_in[0];  // (1000,1,900)
    const float* state0 = (const float*)d_in[1];  // (1,4096)
    const float* W_ih   = (const float*)d_in[2];  // (4096,900)
    const float* W_hh   = (const float*)d_in[3];  // (4096,4096)
    const float* W_out  = (const float*)d_in[4];  // (900,4997)

    float* out    = (float*)d_out;                // outputs: SEQ*IDIM
    float* states = out + (size_t)SEQ * IDIM;     // states : SEQ*HDIM

    float *U = nullptr, *P = nullptr;
    cudaGetSymbolAddress((void**)&U, g_U);
    cudaGetSymbolAddress((void**)&P, g_P);

    cudaFuncSetAttribute(esn_loop_kernel,
                         cudaFuncAttributeMaxDynamicSharedMemorySize, (int)LOOP_SMEM);

    reset_kernel<<<1, 256>>>();

    // U[t][h] = W_ih[h,:] . inp[t,:]            M=4096 N=1000 K=900
    gemm_nt<128, 128><<<dim3(HDIM / 128, (SEQ + 127) / 128), 256>>>(
        W_ih, IDIM, inputs, IDIM, U, HDIM,
        nullptr, nullptr, 0, HDIM, SEQ, IDIM);

    // P[t][i] = W_out[i][0] + W_out[i,1:901] . inp[t,:]   M=900 N=1000 K=900
    gemm_nt<64, 128><<<dim3((IDIM + 63) / 64, (SEQ + 127) / 128), 256>>>(
        W_out + 1, WOLD, inputs, IDIM, P, IDIM,
        nullptr, W_out, WOLD, IDIM, SEQ, IDIM);

    // sequential recurrence: states[t] = tanh(U[t] + W_hh @ states[t-1])
    esn_loop_kernel<<<NBLK, TPB, LOOP_SMEM>>>(W_hh, state0, states);

    // out[t][i] = P[t][i] + W_out[i,901:] . states[t,:]   M=900 N=1000 K=4096
    gemm_nt<64, 128><<<dim3((IDIM + 63) / 64, (SEQ + 127) / 128), 256>>>(
        W_out + 1 + IDIM, WOLD, states, HDIM, out, IDIM,
        P, nullptr, 0, IDIM, SEQ, HDIM);
}

// round 4
// speedup vs baseline: 1.1220x; 1.1220x over previous
#include <cuda_runtime.h>
#include <cstdint>

#define SEQ   1000
#define IDIM  900
#define HDIM  4096
#define WOLD  (HDIM + IDIM + 1)   // 4997, W_out row stride
#define NBLK  148
#define TPB   1024
#define CACHE_ROWS 13
#define LOOP_SMEM ((CACHE_ROWS * HDIM + HDIM) * sizeof(float))   // 229376 B

// ---------------- scratch (static device globals; no allocation) ----------------
__device__ float g_U[SEQ * HDIM];   // W_ih @ inp[t]   (t-major)
__device__ float g_P[SEQ * IDIM];   // bias + input part of readout
__device__ int   g_flags[NBLK];

__device__ __forceinline__ int ld_acq(const int* p) {
    int v;
    asm volatile("ld.acquire.gpu.b32 %0, [%1];" : "=r"(v) : "l"(p) : "memory");
    return v;
}
__device__ __forceinline__ void st_rel(int* p, int v) {
    asm volatile("st.release.gpu.b32 [%0], %1;" :: "l"(p), "r"(v) : "memory");
}
// 32-byte load (8 floats) with L2 evict_last hint — legal width on sm_103.
struct F8 { float4 a, b; };
__device__ __forceinline__ F8 ldg32_evict_last(const void* p) {
    unsigned long long x0, x1, x2, x3;
    asm volatile("ld.global.L2::evict_last.v4.b64 {%0,%1,%2,%3}, [%4];"
                 : "=l"(x0), "=l"(x1), "=l"(x2), "=l"(x3) : "l"(p));
    F8 r;
    r.a.x = __uint_as_float((unsigned)x0); r.a.y = __uint_as_float((unsigned)(x0 >> 32));
    r.a.z = __uint_as_float((unsigned)x1); r.a.w = __uint_as_float((unsigned)(x1 >> 32));
    r.b.x = __uint_as_float((unsigned)x2); r.b.y = __uint_as_float((unsigned)(x2 >> 32));
    r.b.z = __uint_as_float((unsigned)x3); r.b.w = __uint_as_float((unsigned)(x3 >> 32));
    return r;
}

__global__ void reset_kernel() {
    if (threadIdx.x < NBLK) g_flags[threadIdx.x] = 0;
}

// ---------------- persistent recurrence kernel ----------------
// s_{t} = tanh(U[t] + W_hh @ s_{t-1});  states[t] = s_t
// 148 blocks (1/SM). One W_hh row per warp (warps 0..nrows-1); first
// CACHE_ROWS rows of each block's slice live in SMEM for the whole run, the
// rest stream from L2 (32B evict_last loads). Warp 31 (always row-less) is
// the dedicated grid-barrier poller with nanosleep backoff.
__global__ __launch_bounds__(TPB, 1) void esn_loop_kernel(
    const float* __restrict__ W_hh,
    const float* __restrict__ s0,
    float* __restrict__ states)
{
    extern __shared__ float sh[];
    float* w_sh = sh;                      // CACHE_ROWS * HDIM
    float* s_sh = sh + CACHE_ROWS * HDIM;  // HDIM

    const int bid  = blockIdx.x;
    const int tid  = threadIdx.x;
    const int warp = tid >> 5;
    const int lane = tid & 31;

    // 4096 = 148*27 + 100 -> blocks 0..99 get 28 rows, 100..147 get 27
    const int base  = bid * 27 + (bid < 100 ? bid : 100);
    const int nrows = (bid < 100) ? 28 : 27;

    // prologue: cache first CACHE_ROWS rows of this block's slice in SMEM
    {
        const float4* wsrc = (const float4*)(W_hh + (size_t)base * HDIM);
        float4* wdst = (float4*)w_sh;
        for (int i = tid; i < CACHE_ROWS * (HDIM / 4); i += TPB) wdst[i] = wsrc[i];
    }

    const float* s_src = s0;
    const int r = warp;
    const bool active = (r < nrows);
    const bool in_smem = (r < CACHE_ROWS);
    const float* wrow_g = W_hh + (size_t)(base + r) * HDIM;
    const float4* wrow_s = (const float4*)(w_sh + r * HDIM);

    for (int t = 0; t < SEQ; ++t) {
        // stage current state vector into SMEM (HDIM/4 == TPB exactly)
        ((float4*)s_sh)[tid] = ((const float4*)s_src)[tid];
        __syncthreads();

        if (active) {
            const float u = g_U[(size_t)t * HDIM + base + r];  // uniform broadcast
            const float4* sv = (const float4*)s_sh;
            float ax = 0.f, ay = 0.f, az = 0.f, aw = 0.f;

            if (in_smem) {
                #pragma unroll 8
                for (int kk = lane; kk < HDIM / 4; kk += 32) {
                    float4 a = wrow_s[kk];
                    float4 s = sv[kk];
                    ax = fmaf(a.x, s.x, ax); ay = fmaf(a.y, s.y, ay);
                    az = fmaf(a.z, s.z, az); aw = fmaf(a.w, s.w, aw);
                }
            } else {
                // 16 iterations of 32B loads per warp-row (lane covers 8 floats)
                #pragma unroll 4
                for (int kk = lane; kk < HDIM / 8; kk += 32) {
                    F8 w = ldg32_evict_last(wrow_g + kk * 8);
                    float4 s0v = sv[kk * 2];
                    float4 s1v = sv[kk * 2 + 1];
                    ax = fmaf(w.a.x, s0v.x, ax); ay = fmaf(w.a.y, s0v.y, ay);
                    az = fmaf(w.a.z, s0v.z, az); aw = fmaf(w.a.w, s0v.w, aw);
                    ax = fmaf(w.b.x, s1v.x, ax); ay = fmaf(w.b.y, s1v.y, ay);
                    az = fmaf(w.b.z, s1v.z, az); aw = fmaf(w.b.w, s1v.w, aw);
                }
            }
            float acc = (ax + ay) + (az + aw);

            #pragma unroll
            for (int off = 16; off; off >>= 1)
                acc += __shfl_xor_sync(0xffffffffu, acc, off);

            if (lane == 0)
                states[(size_t)t * HDIM + base + r] = tanhf(acc + u);
        }

        __syncthreads();   // all states STGs of this step issued

        if (t < SEQ - 1) {
            if (tid == 0) { __threadfence(); st_rel(&g_flags[bid], t + 1); }
            if (warp == 31) {  // dedicated poller warp (never owns a row)
                bool done;
                do {
                    bool ok = true;
                    for (int i = lane; i < NBLK; i += 32)
                        ok &= (ld_acq(&g_flags[i]) > t);
                    done = __all_sync(0xffffffffu, ok);
                    if (!done) __nanosleep(32);
                } while (!done);
            }
            __syncthreads();   // barrier passed; also protects s_sh reuse
        }

        s_src = states + (size_t)t * HDIM;
    }
}

// ---------------- fp32 GEMM: C[n][m] = (bias[m]) + (Cadd[n][m]) + sum_k A[m][k]*B[n][k]
// A: M x K row stride lda (scalar loads — may be unaligned base / odd lda)
// B: N x K row stride ldb (float4 when aligned)
// 256 threads, BMxBN tile, BK=8, (BM/16)x(BN/16) microtile per thread.
template<int BM, int BN>
__global__ __launch_bounds__(256) void gemm_nt(
    const float* __restrict__ A, int lda,
    const float* __restrict__ B, int ldb,
    float* __restrict__ C, int ldc,
    const float* __restrict__ Cadd,
    const float* __restrict__ bias, int bias_stride,
    int M, int N, int K)
{
    constexpr int BK = 8;
    constexpr int TM = BM / 16;
    constexpr int TN = BN / 16;
    __shared__ float As[BK][BM + 4];
    __shared__ float Bs[BK][BN + 4];

    const int tid = threadIdx.x;
    const int tx = tid & 15;
    const int ty = tid >> 4;
    const int m0 = blockIdx.x * BM;
    const int n0 = blockIdx.y * BN;

    const bool b_vec = ((reinterpret_cast<uintptr_t>(B) & 15) == 0) && ((ldb & 3) == 0);

    float acc[TM][TN];
    #pragma unroll
    for (int i = 0; i < TM; ++i)
        #pragma unroll
        for (int j = 0; j < TN; ++j) acc[i][j] = 0.f;

    for (int kt = 0; kt < K; kt += BK) {
        // ---- load A tile (BM x 8) transposed into As, scalar loads ----
        #pragma unroll
        for (int i = tid; i < BM * 2; i += 256) {
            int m = i >> 1;
            int kq = (i & 1) * 4;
            int gm = m0 + m;
            float v0 = 0.f, v1 = 0.f, v2 = 0.f, v3 = 0.f;
            if (gm < M) {
                const float* p = A + (size_t)gm * lda + (kt + kq);
                int rem = K - (kt + kq);
                if (rem > 0) v0 = p[0];
                if (rem > 1) v1 = p[1];
                if (rem > 2) v2 = p[2];
                if (rem > 3) v3 = p[3];
            }
            As[kq + 0][m] = v0; As[kq + 1][m] = v1;
            As[kq + 2][m] = v2; As[kq + 3][m] = v3;
        }
        // ---- load B tile (BN x 8) transposed into Bs ----
        #pragma unroll
        for (int i = tid; i < BN * 2; i += 256) {
            int n = i >> 1;
            int kq = (i & 1) * 4;
            int gn = n0 + n;
            int gk = kt + kq;
            float v0 = 0.f, v1 = 0.f, v2 = 0.f, v3 = 0.f;
            if (gn < N) {
                const float* p = B + (size_t)gn * ldb + gk;
                int rem = K - gk;
                if (b_vec && rem >= 4) {
                    float4 v = *(const float4*)p;
                    v0 = v.x; v1 = v.y; v2 = v.z; v3 = v.w;
                } else {
                    if (rem > 0) v0 = p[0];
                    if (rem > 1) v1 = p[1];
                    if (rem > 2) v2 = p[2];
                    if (rem > 3) v3 = p[3];
                }
            }
            Bs[kq + 0][n] = v0; Bs[kq + 1][n] = v1;
            Bs[kq + 2][n] = v2; Bs[kq + 3][n] = v3;
        }
        __syncthreads();

        #pragma unroll
        for (int kk = 0; kk < BK; ++kk) {
            float a[TM], b[TN];
            #pragma unroll
            for (int i = 0; i < TM; ++i) a[i] = As[kk][ty * TM + i];
            #pragma unroll
            for (int j = 0; j < TN; ++j) b[j] = Bs[kk][tx * TN + j];
            #pragma unroll
            for (int i = 0; i < TM; ++i)
                #pragma unroll
                for (int j = 0; j < TN; ++j)
                    acc[i][j] = fmaf(a[i], b[j], acc[i][j]);
        }
        __syncthreads();
    }

    // ---- epilogue ----
    #pragma unroll
    for (int i = 0; i < TM; ++i) {
        int gm = m0 + ty * TM + i;
        if (gm >= M) continue;
        float bv = bias ? bias[(size_t)gm * bias_stride] : 0.f;
        #pragma unroll
        for (int j = 0; j < TN; ++j) {
            int gn = n0 + tx * TN + j;
            if (gn >= N) continue;
            float v = acc[i][j] + bv;
            if (Cadd) v += Cadd[(size_t)gn * ldc + gm];
            C[(size_t)gn * ldc + gm] = v;
        }
    }
}

// ---------------- launch ----------------
extern "C" void kernel_launch(void* const* d_in, const int* in_sizes, int n_in,
                              void* d_out, int out_size)
{
    const float* inputs = (const float*)d_in[0];  // (1000,1,900)
    const float* state0 = (const float*)d_in[1];  // (1,4096)
    const float* W_ih   = (const float*)d_in[2];  // (4096,900)
    const float* W_hh   = (const float*)d_in[3];  // (4096,4096)
    const float* W_out  = (const float*)d_in[4];  // (900,4997)

    float* out    = (float*)d_out;                // outputs: SEQ*IDIM
    float* states = out + (size_t)SEQ * IDIM;     // states : SEQ*HDIM

    float *U = nullptr, *P = nullptr;
    cudaGetSymbolAddress((void**)&U, g_U);
    cudaGetSymbolAddress((void**)&P, g_P);

    cudaFuncSetAttribute(esn_loop_kernel,
                         cudaFuncAttributeMaxDynamicSharedMemorySize, (int)LOOP_SMEM);

    reset_kernel<<<1, 256>>>();

    // U[t][h] = W_ih[h,:] . inp[t,:]            M=4096 N=1000 K=900
    gemm_nt<128, 128><<<dim3(HDIM / 128, (SEQ + 127) / 128), 256>>>(
        W_ih, IDIM, inputs, IDIM, U, HDIM,
        nullptr, nullptr, 0, HDIM, SEQ, IDIM);

    // P[t][i] = W_out[i][0] + W_out[i,1:901] . inp[t,:]   M=900 N=1000 K=900
    gemm_nt<64, 128><<<dim3((IDIM + 63) / 64, (SEQ + 127) / 128), 256>>>(
        W_out + 1, WOLD, inputs, IDIM, P, IDIM,
        nullptr, W_out, WOLD, IDIM, SEQ, IDIM);

    // sequential recurrence: states[t] = tanh(U[t] + W_hh @ states[t-1])
    esn_loop_kernel<<<NBLK, TPB, LOOP_SMEM>>>(W_hh, state0, states);

    // out[t][i] = P[t][i] + W_out[i,901:] . states[t,:]   M=900 N=1000 K=4096
    gemm_nt<64, 128><<<dim3((IDIM + 63) / 64, (SEQ + 127) / 128), 256>>>(
        W_out + 1 + IDIM, WOLD, states, HDIM, out, IDIM,
        P, nullptr, 0, IDIM, SEQ, HDIM);
}

// round 5
// speedup vs baseline: 1.8752x; 1.6713x over previous
#include <cuda_runtime.h>
#include <cstdint>

#define SEQ   1000
#define IDIM  900
#define HDIM  4096
#define WOLD  (HDIM + IDIM + 1)   // 4997, W_out row stride
#define NBLK  148
#define TPB   1024
#define CACHE_ROWS 12
#define LOOP_SMEM ((CACHE_ROWS * HDIM + HDIM) * sizeof(float))   // 212992 B

// ---------------- scratch (static device globals; no allocation) ----------------
__device__ float g_U[SEQ * HDIM];   // W_ih @ inp[t]   (t-major)
__device__ float g_P[SEQ * IDIM];   // bias + input part of readout
__device__ int   g_bar;             // monotonic arrival counter

__device__ __forceinline__ int ld_acq(const int* p) {
    int v;
    asm volatile("ld.acquire.gpu.b32 %0, [%1];" : "=r"(v) : "l"(p) : "memory");
    return v;
}
// release-ordered arrival: orders all prior writes (states STGs) before the add
__device__ __forceinline__ void arrive_release(int* p) {
    asm volatile("red.release.gpu.global.add.s32 [%0], 1;" :: "l"(p) : "memory");
}

__global__ void reset_kernel() {
    if (threadIdx.x == 0) g_bar = 0;
}

// ---------------- persistent recurrence kernel ----------------
// s_{t} = tanh(U[t] + W_hh @ s_{t-1});  states[t] = s_t
// 148 blocks (1/SM). Two W_hh rows per warp sharing the s reads; rows
// 0..CACHE_ROWS-1 of each block's slice live in SMEM for the whole run, the
// rest stream from L2. Grid barrier = single monotonic atomic counter:
// one red.release.add per block, single-line acquire-poll by warp 31.
__global__ __launch_bounds__(TPB, 1) void esn_loop_kernel(
    const float* __restrict__ W_hh,
    const float* __restrict__ s0,
    float* __restrict__ states)
{
    extern __shared__ float sh[];
    float* w_sh = sh;                      // CACHE_ROWS * HDIM
    float* s_sh = sh + CACHE_ROWS * HDIM;  // HDIM

    const int bid  = blockIdx.x;
    const int tid  = threadIdx.x;
    const int warp = tid >> 5;
    const int lane = tid & 31;

    // 4096 = 148*27 + 100 -> blocks 0..99 get 28 rows, 100..147 get 27
    const int base  = bid * 27 + (bid < 100 ? bid : 100);
    const int nrows = (bid < 100) ? 28 : 27;

    // prologue: cache first CACHE_ROWS rows of this block's slice in SMEM
    {
        const float4* wsrc = (const float4*)(W_hh + (size_t)base * HDIM);
        float4* wdst = (float4*)w_sh;
        for (int i = tid; i < CACHE_ROWS * (HDIM / 4); i += TPB) wdst[i] = wsrc[i];
    }

    const float* s_src = s0;
    const int r0 = 2 * warp;                 // this warp's first row
    const bool in_smem = (r0 + 1 < CACHE_ROWS) || (r0 + 2 <= CACHE_ROWS); // r0,r0+1 < 12
    const float4* w0g = (const float4*)(W_hh + (size_t)(base + r0) * HDIM);
    const float4* w1g = (const float4*)(W_hh + (size_t)(base + r0 + 1) * HDIM);
    const float4* w0s = (const float4*)(w_sh + r0 * HDIM);
    const float4* w1s = (const float4*)(w_sh + (r0 + 1) * HDIM);

    for (int t = 0; t < SEQ; ++t) {
        // stage current state vector into SMEM (HDIM/4 == TPB exactly)
        ((float4*)s_sh)[tid] = ((const float4*)s_src)[tid];
        __syncthreads();

        if (r0 < nrows) {
            const bool has1 = (r0 + 1 < nrows);
            const float4* sv = (const float4*)s_sh;
            float a0x = 0.f, a0y = 0.f, a1x = 0.f, a1y = 0.f;

            if (in_smem) {
                #pragma unroll 4
                for (int kk = lane; kk < HDIM / 4; kk += 32) {
                    float4 s = sv[kk];
                    float4 a = w0s[kk];
                    float4 b = w1s[kk];
                    a0x = fmaf(a.x, s.x, a0x); a0y = fmaf(a.y, s.y, a0y);
                    a0x = fmaf(a.z, s.z, a0x); a0y = fmaf(a.w, s.w, a0y);
                    a1x = fmaf(b.x, s.x, a1x); a1y = fmaf(b.y, s.y, a1y);
                    a1x = fmaf(b.z, s.z, a1x); a1y = fmaf(b.w, s.w, a1y);
                }
            } else {
                #pragma unroll 4
                for (int kk = lane; kk < HDIM / 4; kk += 32) {
                    float4 a = w0g[kk];
                    float4 b = has1 ? w1g[kk] : make_float4(0.f, 0.f, 0.f, 0.f);
                    float4 s = sv[kk];
                    a0x = fmaf(a.x, s.x, a0x); a0y = fmaf(a.y, s.y, a0y);
                    a0x = fmaf(a.z, s.z, a0x); a0y = fmaf(a.w, s.w, a0y);
                    a1x = fmaf(b.x, s.x, a1x); a1y = fmaf(b.y, s.y, a1y);
                    a1x = fmaf(b.z, s.z, a1x); a1y = fmaf(b.w, s.w, a1y);
                }
            }
            float acc0 = a0x + a0y;
            float acc1 = a1x + a1y;

            #pragma unroll
            for (int off = 16; off; off >>= 1) {
                acc0 += __shfl_xor_sync(0xffffffffu, acc0, off);
                acc1 += __shfl_xor_sync(0xffffffffu, acc1, off);
            }
            if (lane == 0) {
                const size_t o = (size_t)t * HDIM + base + r0;
                const float* up = &g_U[o];
                states[o] = tanhf(acc0 + up[0]);
                if (has1) states[o + 1] = tanhf(acc1 + up[1]);
            }
        }

        __syncthreads();   // all states STGs of this step issued

        if (t < SEQ - 1) {
            if (tid == 0) arrive_release(&g_bar);   // release: orders the STGs
            if (warp == 31) {                       // dedicated poller warp
                const int target = (t + 1) * NBLK;
                while (ld_acq(&g_bar) < target) { __nanosleep(32); }
            }
            __syncthreads();   // barrier passed; also protects s_sh reuse
        }

        s_src = states + (size_t)t * HDIM;
    }
}

// ---------------- fp32 GEMM: C[n][m] = (bias[m]) + (Cadd[n][m]) + sum_k A[m][k]*B[n][k]
// A: M x K row stride lda (scalar loads — may be unaligned base / odd lda)
// B: N x K row stride ldb (float4 when aligned)
// 256 threads, BMxBN tile, BK=8, (BM/16)x(BN/16) microtile per thread.
template<int BM, int BN>
__global__ __launch_bounds__(256) void gemm_nt(
    const float* __restrict__ A, int lda,
    const float* __restrict__ B, int ldb,
    float* __restrict__ C, int ldc,
    const float* __restrict__ Cadd,
    const float* __restrict__ bias, int bias_stride,
    int M, int N, int K)
{
    constexpr int BK = 8;
    constexpr int TM = BM / 16;
    constexpr int TN = BN / 16;
    __shared__ float As[BK][BM + 4];
    __shared__ float Bs[BK][BN + 4];

    const int tid = threadIdx.x;
    const int tx = tid & 15;
    const int ty = tid >> 4;
    const int m0 = blockIdx.x * BM;
    const int n0 = blockIdx.y * BN;

    const bool b_vec = ((reinterpret_cast<uintptr_t>(B) & 15) == 0) && ((ldb & 3) == 0);

    float acc[TM][TN];
    #pragma unroll
    for (int i = 0; i < TM; ++i)
        #pragma unroll
        for (int j = 0; j < TN; ++j) acc[i][j] = 0.f;

    for (int kt = 0; kt < K; kt += BK) {
        // ---- load A tile (BM x 8) transposed into As, scalar loads ----
        #pragma unroll
        for (int i = tid; i < BM * 2; i += 256) {
            int m = i >> 1;
            int kq = (i & 1) * 4;
            int gm = m0 + m;
            float v0 = 0.f, v1 = 0.f, v2 = 0.f, v3 = 0.f;
            if (gm < M) {
                const float* p = A + (size_t)gm * lda + (kt + kq);
                int rem = K - (kt + kq);
                if (rem > 0) v0 = p[0];
                if (rem > 1) v1 = p[1];
                if (rem > 2) v2 = p[2];
                if (rem > 3) v3 = p[3];
            }
            As[kq + 0][m] = v0; As[kq + 1][m] = v1;
            As[kq + 2][m] = v2; As[kq + 3][m] = v3;
        }
        // ---- load B tile (BN x 8) transposed into Bs ----
        #pragma unroll
        for (int i = tid; i < BN * 2; i += 256) {
            int n = i >> 1;
            int kq = (i & 1) * 4;
            int gn = n0 + n;
            int gk = kt + kq;
            float v0 = 0.f, v1 = 0.f, v2 = 0.f, v3 = 0.f;
            if (gn < N) {
                const float* p = B + (size_t)gn * ldb + gk;
                int rem = K - gk;
                if (b_vec && rem >= 4) {
                    float4 v = *(const float4*)p;
                    v0 = v.x; v1 = v.y; v2 = v.z; v3 = v.w;
                } else {
                    if (rem > 0) v0 = p[0];
                    if (rem > 1) v1 = p[1];
                    if (rem > 2) v2 = p[2];
                    if (rem > 3) v3 = p[3];
                }
            }
            Bs[kq + 0][n] = v0; Bs[kq + 1][n] = v1;
            Bs[kq + 2][n] = v2; Bs[kq + 3][n] = v3;
        }
        __syncthreads();

        #pragma unroll
        for (int kk = 0; kk < BK; ++kk) {
            float a[TM], b[TN];
            #pragma unroll
            for (int i = 0; i < TM; ++i) a[i] = As[kk][ty * TM + i];
            #pragma unroll
            for (int j = 0; j < TN; ++j) b[j] = Bs[kk][tx * TN + j];
            #pragma unroll
            for (int i = 0; i < TM; ++i)
                #pragma unroll
                for (int j = 0; j < TN; ++j)
                    acc[i][j] = fmaf(a[i], b[j], acc[i][j]);
        }
        __syncthreads();
    }

    // ---- epilogue ----
    #pragma unroll
    for (int i = 0; i < TM; ++i) {
        int gm = m0 + ty * TM + i;
        if (gm >= M) continue;
        float bv = bias ? bias[(size_t)gm * bias_stride] : 0.f;
        #pragma unroll
        for (int j = 0; j < TN; ++j) {
            int gn = n0 + tx * TN + j;
            if (gn >= N) continue;
            float v = acc[i][j] + bv;
            if (Cadd) v += Cadd[(size_t)gn * ldc + gm];
            C[(size_t)gn * ldc + gm] = v;
        }
    }
}

// ---------------- launch ----------------
extern "C" void kernel_launch(void* const* d_in, const int* in_sizes, int n_in,
                              void* d_out, int out_size)
{
    const float* inputs = (const float*)d_in[0];  // (1000,1,900)
    const float* state0 = (const float*)d_in[1];  // (1,4096)
    const float* W_ih   = (const float*)d_in[2];  // (4096,900)
    const float* W_hh   = (const float*)d_in[3];  // (4096,4096)
    const float* W_out  = (const float*)d_in[4];  // (900,4997)

    float* out    = (float*)d_out;                // outputs: SEQ*IDIM
    float* states = out + (size_t)SEQ * IDIM;     // states : SEQ*HDIM

    float *U = nullptr, *P = nullptr;
    cudaGetSymbolAddress((void**)&U, g_U);
    cudaGetSymbolAddress((void**)&P, g_P);

    cudaFuncSetAttribute(esn_loop_kernel,
                         cudaFuncAttributeMaxDynamicSharedMemorySize, (int)LOOP_SMEM);

    reset_kernel<<<1, 32>>>();

    // U[t][h] = W_ih[h,:] . inp[t,:]            M=4096 N=1000 K=900
    gemm_nt<128, 128><<<dim3(HDIM / 128, (SEQ + 127) / 128), 256>>>(
        W_ih, IDIM, inputs, IDIM, U, HDIM,
        nullptr, nullptr, 0, HDIM, SEQ, IDIM);

    // P[t][i] = W_out[i][0] + W_out[i,1:901] . inp[t,:]   M=900 N=1000 K=900
    gemm_nt<64, 128><<<dim3((IDIM + 63) / 64, (SEQ + 127) / 128), 256>>>(
        W_out + 1, WOLD, inputs, IDIM, P, IDIM,
        nullptr, W_out, WOLD, IDIM, SEQ, IDIM);

    // sequential recurrence: states[t] = tanh(U[t] + W_hh @ states[t-1])
    esn_loop_kernel<<<NBLK, TPB, LOOP_SMEM>>>(W_hh, state0, states);

    // out[t][i] = P[t][i] + W_out[i,901:] . states[t,:]   M=900 N=1000 K=4096
    gemm_nt<64, 128><<<dim3((IDIM + 63) / 64, (SEQ + 127) / 128), 256>>>(
        W_out + 1 + IDIM, WOLD, states, HDIM, out, IDIM,
        P, nullptr, 0, IDIM, SEQ, HDIM);
}